// round 7
// baseline (speedup 1.0000x reference)
#include <cuda_runtime.h>
#include <cuda_bf16.h>
#include <cstdint>
#include <math.h>

namespace {
constexpr int Bv=8, SQ=2048, SK=2048, Dv=256;
constexpr int BQ=64, BK=64, QT=SQ/BQ;   // 32 q-tiles
constexpr int NITEMS=QT*Bv;             // 256 work items
constexpr float SCALE=0.0625f, EPSV=1e-7f;
// smem byte offsets
constexpr int O_QH=0, O_QL=32768, O_KH=65536, O_KL=98304, O_VH=131072, O_VL=163840;
constexpr int O_PH=196608, O_PL=204800;
constexpr int O_MSK=212992, O_RMAX=213248, O_LSUM=214272, O_LINV=215296, O_WORK=215552;
constexpr int SMEM_SZ=215808;
constexpr size_t NE=(size_t)Bv*SQ*Dv;
}

__device__ uint4 g_Qh[NE/8], g_Ql[NE/8], g_Kh[NE/8], g_Kl[NE/8], g_Vh[NE/8], g_Vl[NE/8];
__device__ float g_maskf[Bv*SK];
__device__ int g_fA, g_fB, g_ctr;

__device__ __forceinline__ uint32_t s2u(const void* p){
    uint32_t a; asm("{ .reg .u64 t; cvta.to.shared.u64 t,%1; cvt.u32.u64 %0,t; }":"=r"(a):"l"(p)); return a;
}
__device__ __forceinline__ void ldsm4(uint32_t a, uint32_t* r){
    asm volatile("ldmatrix.sync.aligned.m8n8.x4.shared.b16 {%0,%1,%2,%3},[%4];"
        :"=r"(r[0]),"=r"(r[1]),"=r"(r[2]),"=r"(r[3]):"r"(a));
}
__device__ __forceinline__ void ldsm4t(uint32_t a, uint32_t* r){
    asm volatile("ldmatrix.sync.aligned.m8n8.x4.trans.shared.b16 {%0,%1,%2,%3},[%4];"
        :"=r"(r[0]),"=r"(r[1]),"=r"(r[2]),"=r"(r[3]):"r"(a));
}
__device__ __forceinline__ void mma16816(float* c, const uint32_t* a, const uint32_t* b){
    asm volatile("mma.sync.aligned.m16n8k16.row.col.f32.bf16.bf16.f32 "
        "{%0,%1,%2,%3},{%4,%5,%6,%7},{%8,%9},{%0,%1,%2,%3};"
        :"+f"(c[0]),"+f"(c[1]),"+f"(c[2]),"+f"(c[3])
        :"r"(a[0]),"r"(a[1]),"r"(a[2]),"r"(a[3]),"r"(b[0]),"r"(b[1]));
}
#define CPCOMMIT() asm volatile("cp.async.commit_group;":::"memory")
#define CPWAIT1()  asm volatile("cp.async.wait_group 1;":::"memory")
// 64x256 bf16 tile (32KB) gmem -> swizzled smem via cp.async; 512 threads
__device__ __forceinline__ void ldtile(uint32_t sbase, const uint4* g, int tid){
    #pragma unroll
    for(int i=0;i<4;i++){
        int idx=i*512+tid, r=idx>>5, c=idx&31;
        uint32_t d=sbase+(uint32_t)(((r<<5)+(c^(r&7)))<<4);
        asm volatile("cp.async.cg.shared.global [%0],[%1],16;"::"r"(d),"l"(g+(size_t)r*32+c));
    }
}

// ---------------- prologues (3 launches) ----------------
__global__ void zero_k(){ g_fA=0; g_fB=0; }
// fused: split Q/K/V into bf16 hi/lo; blocks <32 also scan mask bytes
__global__ void splitqkv_k(const float* __restrict__ Q, const float* __restrict__ K,
                           const float* __restrict__ V, const unsigned char* __restrict__ m){
    const int blk=blockIdx.x, which=blk>>11, lb=blk&2047;
    const float* X = which==0?Q:(which==1?K:V);
    uint4* H = which==0?g_Qh:(which==1?g_Kh:g_Vh);
    uint4* L = which==0?g_Ql:(which==1?g_Kl:g_Vl);
    const float sc = which==0?SCALE:1.f;
    size_t i=((size_t)lb*256+threadIdx.x)*8;
    float4 x0=*(const float4*)(X+i), x1=*(const float4*)(X+i+4);
    float v[8]={x0.x,x0.y,x0.z,x0.w,x1.x,x1.y,x1.z,x1.w};
    __nv_bfloat162 h[4], l[4];
    #pragma unroll
    for(int j=0;j<4;j++){
        float a=v[2*j]*sc, b=v[2*j+1]*sc;
        __nv_bfloat162 hh=__floats2bfloat162_rn(a,b);
        h[j]=hh;
        l[j]=__floats2bfloat162_rn(a-__low2float(hh), b-__high2float(hh));
    }
    H[i/8]=*(uint4*)h; L[i/8]=*(uint4*)l;
    if(blk<32){
        int a=0,b=0;
        int base=blk*512+threadIdx.x*2;
        #pragma unroll
        for(int j=0;j<2;j++){
            int idx=base+j;
            if(idx<Bv*SK && m[idx]){ if((idx&3)==0)b=1; else a=1; }
        }
        if(a)atomicOr(&g_fA,1);
        if(b)atomicOr(&g_fB,1);
    }
}
__global__ void conv_k(const void* __restrict__ m){
    int i=blockIdx.x*blockDim.x+threadIdx.x;
    if(i==0) g_ctr=0;
    if(i>=Bv*SK)return;
    int A=g_fA,B=g_fB; bool v;
    if(A&&B)v=((const unsigned char*)m)[i]!=0;
    else if(B)v=((const int*)m)[i]!=0;
    else if(A)v=((const float*)m)[i]!=0.f;
    else v=false;
    g_maskf[i]=v?1.f:0.f;
}

// ---------------- persistent attention ----------------
__global__ void __launch_bounds__(512,1)
attn_mma(float* __restrict__ Out){
    extern __shared__ char sm[];
    const uint32_t sb=s2u(sm);
    const int tid=threadIdx.x, wid=tid>>5, lane=tid&31;
    const int lr=lane>>2, lc=lane&3, g=lane>>3, rin=lane&7;
    const int g2=g>>1, gk=g&1;
    const int mwQ=wid>>2, nwQ=wid&3;     // QK: 4m x 4n, warp tile 16x16
    const int mw2=wid>>3, nw8=wid&7;     // PV: 2m x 8n, warp tile 32x32

    float* MSKs=(float*)(sm+O_MSK);  float* RMAX=(float*)(sm+O_RMAX);
    float* LSUM=(float*)(sm+O_LSUM); float* LINV=(float*)(sm+O_LINV);
    int* WORK=(int*)(sm+O_WORK);

    const int rA=mwQ*16+gk*8+rin;
    const uint32_t aQH=sb+O_QH+rA*512, aQL=sb+O_QL+rA*512;
    const int rB=nwQ*16+g2*8+rin;
    const uint32_t bKH=sb+O_KH+rB*512, bKL=sb+O_KL+rB*512;
    const int rP=mw2*32+gk*8+rin;
    const uint32_t aPH=sb+O_PH+rP*128, aPL=sb+O_PL+rP*128;
    const int rV=gk*8+rin;
    const uint32_t bVH=sb+O_VH+rV*512, bVL=sb+O_VL+rV*512;
    const int srow0=mwQ*16+lr, srow1=srow0+8;
    const int orow0=mw2*32+lr;   // + mt*16 (+8)

    if(tid==0) WORK[0]=atomicAdd(&g_ctr,1);
    __syncthreads();

    while(true){
        const int w=WORK[0];
        if(w>=NITEMS) break;
        const int bi=w&7, qt=QT-1-(w>>3), q0=qt*BQ;
        const size_t rowQ=(size_t)bi*SQ+q0, rowKV=(size_t)bi*SK;

        float o[2][4][4];
        #pragma unroll
        for(int a=0;a<2;a++)
            #pragma unroll
            for(int b=0;b<4;b++){o[a][b][0]=0.f;o[a][b][1]=0.f;o[a][b][2]=0.f;o[a][b][3]=0.f;}
        float ls0=0.f, ls1=0.f;
        float m_s0=-INFINITY, m_s1=-INFINITY;
        float m_o[2][2]={{-INFINITY,-INFINITY},{-INFINITY,-INFINITY}};
        uint32_t qhr[8][4];

        ldtile(sb+O_QH, g_Qh+rowQ*32, tid); ldtile(sb+O_QL, g_Ql+rowQ*32, tid); CPCOMMIT();
        ldtile(sb+O_KH, g_Kh+rowKV*32, tid); ldtile(sb+O_KL, g_Kl+rowKV*32, tid); CPCOMMIT();

        for(int kt=0;kt<=qt;++kt){
            const int k0=kt*BK;
            ldtile(sb+O_VH, g_Vh+(rowKV+k0)*32, tid); ldtile(sb+O_VL, g_Vl+(rowKV+k0)*32, tid); CPCOMMIT();
            if(tid<64) MSKs[tid]=g_maskf[bi*SK+k0+tid];
            CPWAIT1(); __syncthreads();          // K(kt) (+Q first iter) ready

            if(kt==0){
                #pragma unroll
                for(int ks=0;ks<8;++ks)
                    ldsm4(aQH+(uint32_t)(((2*ks+g2)^rin)<<4), qhr[ks]);
            }
            // ---- S = Q.K^T (bf16x3) ----
            float c4[2][4];
            #pragma unroll
            for(int t=0;t<2;++t){c4[t][0]=0.f;c4[t][1]=0.f;c4[t][2]=0.f;c4[t][3]=0.f;}
            #pragma unroll
            for(int ks=0;ks<16;++ks){
                uint32_t ah[4],al[4],bh[4],bl[4];
                uint32_t ca=(uint32_t)(((2*ks+g2)^rin)<<4);
                if(ks<8){ ah[0]=qhr[ks][0];ah[1]=qhr[ks][1];ah[2]=qhr[ks][2];ah[3]=qhr[ks][3]; }
                else ldsm4(aQH+ca,ah);
                ldsm4(aQL+ca,al);
                uint32_t cb=(uint32_t)(((2*ks+gk)^rin)<<4);
                ldsm4(bKH+cb,bh); ldsm4(bKL+cb,bl);
                mma16816(c4[0],ah,bh); mma16816(c4[0],ah,bl); mma16816(c4[0],al,bh);
                mma16816(c4[1],ah,bh+2); mma16816(c4[1],ah,bl+2); mma16816(c4[1],al,bh+2);
            }
            // ---- tile row max (pre-mask) -> RMAX[nwQ][row] ----
            float t0=fmaxf(fmaxf(c4[0][0],c4[0][1]),fmaxf(c4[1][0],c4[1][1]));
            float t1=fmaxf(fmaxf(c4[0][2],c4[0][3]),fmaxf(c4[1][2],c4[1][3]));
            t0=fmaxf(t0,__shfl_xor_sync(~0u,t0,1)); t0=fmaxf(t0,__shfl_xor_sync(~0u,t0,2));
            t1=fmaxf(t1,__shfl_xor_sync(~0u,t1,1)); t1=fmaxf(t1,__shfl_xor_sync(~0u,t1,2));
            if(lc==0){ RMAX[nwQ*64+srow0]=t0; RMAX[nwQ*64+srow1]=t1; }
            __syncthreads();                      // RMAX visible; K buffer free
            if(kt<qt){
                ldtile(sb+O_KH, g_Kh+(rowKV+k0+BK)*32, tid);
                ldtile(sb+O_KL, g_Kl+(rowKV+k0+BK)*32, tid);
            }
            CPCOMMIT();

            // ---- per-thread running max / alpha (no serialization) ----
            float v0=fmaxf(fmaxf(RMAX[srow0],RMAX[64+srow0]),fmaxf(RMAX[128+srow0],RMAX[192+srow0]));
            float v1=fmaxf(fmaxf(RMAX[srow1],RMAX[64+srow1]),fmaxf(RMAX[128+srow1],RMAX[192+srow1]));
            float mn0=fmaxf(m_s0,v0), mn1=fmaxf(m_s1,v1);
            float a0=__expf(m_s0-mn0), a1=__expf(m_s1-mn1);
            m_s0=mn0; m_s1=mn1;
            float ao[2][2];
            #pragma unroll
            for(int mt=0;mt<2;++mt)
                #pragma unroll
                for(int h=0;h<2;++h){
                    int rr=orow0+mt*16+h*8;
                    float tv=fmaxf(fmaxf(RMAX[rr],RMAX[64+rr]),fmaxf(RMAX[128+rr],RMAX[192+rr]));
                    float mo=fmaxf(m_o[mt][h],tv);
                    ao[mt][h]=__expf(m_o[mt][h]-mo);
                    m_o[mt][h]=mo;
                }

            // ---- P = exp(S-m)*mask(*causal) -> smem bf16 hi/lo ----
            float rs0=0.f, rs1=0.f;
            const bool diag=(kt==qt);
            #pragma unroll
            for(int t=0;t<2;++t){
                int col=nwQ*16+t*8+2*lc;
                float mk0=MSKs[col], mk1=MSKs[col+1];
                float p00=__expf(c4[t][0]-mn0)*mk0, p01=__expf(c4[t][1]-mn0)*mk1;
                float p10=__expf(c4[t][2]-mn1)*mk0, p11=__expf(c4[t][3]-mn1)*mk1;
                if(diag){
                    if(col>srow0)p00=0.f; if(col+1>srow0)p01=0.f;
                    if(col>srow1)p10=0.f; if(col+1>srow1)p11=0.f;
                }
                rs0+=p00+p01; rs1+=p10+p11;
                __nv_bfloat162 h0=__floats2bfloat162_rn(p00,p01);
                __nv_bfloat162 l0=__floats2bfloat162_rn(p00-__low2float(h0),p01-__high2float(h0));
                __nv_bfloat162 h1=__floats2bfloat162_rn(p10,p11);
                __nv_bfloat162 l1=__floats2bfloat162_rn(p10-__low2float(h1),p11-__high2float(h1));
                int ch=nwQ*2+t;
                uint32_t d0=(uint32_t)(srow0*128+((ch^(srow0&7))<<4)+4*lc);
                uint32_t d1=(uint32_t)(srow1*128+((ch^(srow1&7))<<4)+4*lc);
                *(__nv_bfloat162*)(sm+O_PH+d0)=h0; *(__nv_bfloat162*)(sm+O_PL+d0)=l0;
                *(__nv_bfloat162*)(sm+O_PH+d1)=h1; *(__nv_bfloat162*)(sm+O_PL+d1)=l1;
            }
            rs0+=__shfl_xor_sync(~0u,rs0,1); rs0+=__shfl_xor_sync(~0u,rs0,2);
            rs1+=__shfl_xor_sync(~0u,rs1,1); rs1+=__shfl_xor_sync(~0u,rs1,2);
            ls0=ls0*a0+rs0; ls1=ls1*a1+rs1;
            // ---- O rescale ----
            #pragma unroll
            for(int mt=0;mt<2;++mt){
                #pragma unroll
                for(int j=0;j<4;++j){
                    o[mt][j][0]*=ao[mt][0]; o[mt][j][1]*=ao[mt][0];
                    o[mt][j][2]*=ao[mt][1]; o[mt][j][3]*=ao[mt][1];
                }
            }
            CPWAIT1(); __syncthreads();          // P visible; V(kt) ready

            // ---- O += P.V (bf16x3) ----
            #pragma unroll
            for(int ks2=0;ks2<4;++ks2){
                uint32_t vh0[4],vl0[4],vh1[4],vl1[4];
                uint32_t rv=(uint32_t)(ks2*16*512);
                uint32_t cv0=(uint32_t)(((nw8*4+g2)^rin)<<4);
                uint32_t cv1=(uint32_t)(((nw8*4+2+g2)^rin)<<4);
                ldsm4t(bVH+rv+cv0,vh0); ldsm4t(bVL+rv+cv0,vl0);
                ldsm4t(bVH+rv+cv1,vh1); ldsm4t(bVL+rv+cv1,vl1);
                #pragma unroll
                for(int mt=0;mt<2;++mt){
                    uint32_t ph4[4],pl4[4];
                    uint32_t cp2=(uint32_t)(mt*16*128+(((2*ks2+g2)^rin)<<4));
                    ldsm4(aPH+cp2,ph4); ldsm4(aPL+cp2,pl4);
                    mma16816(o[mt][0],ph4,vh0); mma16816(o[mt][0],ph4,vl0); mma16816(o[mt][0],pl4,vh0);
                    mma16816(o[mt][1],ph4,vh0+2); mma16816(o[mt][1],ph4,vl0+2); mma16816(o[mt][1],pl4,vh0+2);
                    mma16816(o[mt][2],ph4,vh1); mma16816(o[mt][2],ph4,vl1); mma16816(o[mt][2],pl4,vh1);
                    mma16816(o[mt][3],ph4,vh1+2); mma16816(o[mt][3],ph4,vl1+2); mma16816(o[mt][3],pl4,vh1+2);
                }
            }
            __syncthreads();                     // V + P buffers free
        }

        // ---- epilogue ----
        if(lc==0){ LSUM[nwQ*64+srow0]=ls0; LSUM[nwQ*64+srow1]=ls1; }
        __syncthreads();
        if(tid<64) LINV[tid]=1.f/(LSUM[tid]+LSUM[64+tid]+LSUM[128+tid]+LSUM[192+tid]+EPSV);
        __syncthreads();
        #pragma unroll
        for(int mt=0;mt<2;++mt){
            int r0=mw2*32+mt*16+lr, r1=r0+8;
            float i0=LINV[r0], i1=LINV[r1];
            float* out0=Out+(size_t)(bi*SQ+q0+r0)*Dv;
            float* out1=Out+(size_t)(bi*SQ+q0+r1)*Dv;
            #pragma unroll
            for(int j=0;j<4;++j){
                int col=nw8*32+j*8+2*lc;
                *(float2*)(out0+col)=make_float2(o[mt][j][0]*i0,o[mt][j][1]*i0);
                *(float2*)(out1+col)=make_float2(o[mt][j][2]*i1,o[mt][j][3]*i1);
            }
        }
        if(tid==0) WORK[0]=atomicAdd(&g_ctr,1);
        __syncthreads();
    }
}

extern "C" void kernel_launch(void* const* d_in, const int* in_sizes, int n_in,
                              void* d_out, int out_size){
    (void)in_sizes; (void)n_in; (void)out_size;
    const float* Q=(const float*)d_in[0];
    const float* K=(const float*)d_in[1];
    const float* V=(const float*)d_in[2];
    const void*  M=d_in[3];
    float*       O=(float*)d_out;

    zero_k<<<1,1>>>();
    splitqkv_k<<<3*2048,256>>>(Q,K,V,(const unsigned char*)M);
    conv_k<<<(Bv*SK+255)/256,256>>>(M);

    cudaFuncSetAttribute(attn_mma, cudaFuncAttributeMaxDynamicSharedMemorySize, SMEM_SZ);
    attn_mma<<<148,512,SMEM_SZ>>>(O);
}

// round 12
// speedup vs baseline: 1.1421x; 1.1421x over previous
#include <cuda_runtime.h>
#include <cuda_bf16.h>
#include <cstdint>
#include <math.h>

namespace {
constexpr int Bv=8, SQ=2048, SK=2048, Dv=256;
constexpr int BQ=64, BK=64, QT=SQ/BQ;   // 32 q-tiles
constexpr float SCALE=0.0625f, EPSV=1e-7f;
// smem byte offsets
constexpr int O_QH=0, O_QL=32768, O_KH=65536, O_KL=98304, O_VH=131072, O_VL=163840;
constexpr int O_PH=196608, O_PL=204800;
constexpr int O_MSK=212992;                       // 128 floats (double-buffered, parity by kt)
constexpr int O_RMAX=213504, O_ALPHA=214528, O_MROW=214784, O_LSUM=215040, O_LINV=216064;
constexpr int SMEM_SZ=216320;
constexpr size_t NE=(size_t)Bv*SQ*Dv;
}

__device__ uint4 g_Qh[NE/8], g_Ql[NE/8], g_Kh[NE/8], g_Kl[NE/8], g_Vh[NE/8], g_Vl[NE/8];
__device__ float g_maskf[Bv*SK];
__device__ int g_fA, g_fB;

__device__ __forceinline__ uint32_t s2u(const void* p){
    uint32_t a; asm("{ .reg .u64 t; cvta.to.shared.u64 t,%1; cvt.u32.u64 %0,t; }":"=r"(a):"l"(p)); return a;
}
__device__ __forceinline__ void ldsm4(uint32_t a, uint32_t* r){
    asm volatile("ldmatrix.sync.aligned.m8n8.x4.shared.b16 {%0,%1,%2,%3},[%4];"
        :"=r"(r[0]),"=r"(r[1]),"=r"(r[2]),"=r"(r[3]):"r"(a));
}
__device__ __forceinline__ void ldsm4t(uint32_t a, uint32_t* r){
    asm volatile("ldmatrix.sync.aligned.m8n8.x4.trans.shared.b16 {%0,%1,%2,%3},[%4];"
        :"=r"(r[0]),"=r"(r[1]),"=r"(r[2]),"=r"(r[3]):"r"(a));
}
__device__ __forceinline__ void mma16816(float* c, const uint32_t* a, const uint32_t* b){
    asm volatile("mma.sync.aligned.m16n8k16.row.col.f32.bf16.bf16.f32 "
        "{%0,%1,%2,%3},{%4,%5,%6,%7},{%8,%9},{%0,%1,%2,%3};"
        :"+f"(c[0]),"+f"(c[1]),"+f"(c[2]),"+f"(c[3])
        :"r"(a[0]),"r"(a[1]),"r"(a[2]),"r"(a[3]),"r"(b[0]),"r"(b[1]));
}
#define CPCOMMIT() asm volatile("cp.async.commit_group;":::"memory")
#define CPW0() asm volatile("cp.async.wait_group 0;":::"memory")
#define CPW1() asm volatile("cp.async.wait_group 1;":::"memory")
#define CPW2() asm volatile("cp.async.wait_group 2;":::"memory")
#define CPW3() asm volatile("cp.async.wait_group 3;":::"memory")
#define CPA(d,s) asm volatile("cp.async.cg.shared.global [%0],[%1],16;"::"r"(d),"l"(s))

// 64x256 bf16 tile (32KB) gmem -> swizzled smem; 512 threads
__device__ __forceinline__ void ldtile(uint32_t sbase, const uint4* g, int tid){
    #pragma unroll
    for(int i=0;i<4;i++){
        int idx=i*512+tid, r=idx>>5, c=idx&31;
        uint32_t d=sbase+(uint32_t)(((r<<5)+(c^(r&7)))<<4);
        CPA(d, g+(size_t)r*32+c);
    }
}
// depth half h (uint4 cols h*16..h*16+15) of hi+lo 64x256 tiles
__device__ __forceinline__ void ldKdep(uint32_t sH, uint32_t sL, const uint4* gH, const uint4* gL, int h, int tid){
    #pragma unroll
    for(int i=0;i<2;i++){
        int idx=i*512+tid, r=idx>>4, c=(idx&15)+h*16;
        uint32_t d=(uint32_t)(((r<<5)+(c^(r&7)))<<4);
        CPA(sH+d, gH+(size_t)r*32+c);
        CPA(sL+d, gL+(size_t)r*32+c);
    }
}
// row half h (rows h*32..h*32+31) of hi+lo V tiles
__device__ __forceinline__ void ldVrow(uint32_t sH, uint32_t sL, const uint4* gH, const uint4* gL, int h, int tid){
    #pragma unroll
    for(int i=0;i<2;i++){
        int idx=i*512+tid, r=h*32+(idx>>5), c=idx&31;
        uint32_t d=(uint32_t)(((r<<5)+(c^(r&7)))<<4);
        CPA(sH+d, gH+(size_t)r*32+c);
        CPA(sL+d, gL+(size_t)r*32+c);
    }
}

// ---------------- prologues (3 launches) ----------------
__global__ void zero_k(){ g_fA=0; g_fB=0; }
__global__ void splitqkv_k(const float* __restrict__ Q, const float* __restrict__ K,
                           const float* __restrict__ V, const unsigned char* __restrict__ m){
    const int blk=blockIdx.x, which=blk>>11, lb=blk&2047;
    const float* X = which==0?Q:(which==1?K:V);
    uint4* H = which==0?g_Qh:(which==1?g_Kh:g_Vh);
    uint4* L = which==0?g_Ql:(which==1?g_Kl:g_Vl);
    const float sc = which==0?SCALE:1.f;
    size_t i=((size_t)lb*256+threadIdx.x)*8;
    float4 x0=*(const float4*)(X+i), x1=*(const float4*)(X+i+4);
    float v[8]={x0.x,x0.y,x0.z,x0.w,x1.x,x1.y,x1.z,x1.w};
    __nv_bfloat162 h[4], l[4];
    #pragma unroll
    for(int j=0;j<4;j++){
        float a=v[2*j]*sc, b=v[2*j+1]*sc;
        __nv_bfloat162 hh=__floats2bfloat162_rn(a,b);
        h[j]=hh;
        l[j]=__floats2bfloat162_rn(a-__low2float(hh), b-__high2float(hh));
    }
    H[i/8]=*(uint4*)h; L[i/8]=*(uint4*)l;
    if(blk<32){
        int a=0,b=0;
        int base=blk*512+threadIdx.x*2;
        #pragma unroll
        for(int j=0;j<2;j++){
            int idx=base+j;
            if(idx<Bv*SK && m[idx]){ if((idx&3)==0)b=1; else a=1; }
        }
        if(a)atomicOr(&g_fA,1);
        if(b)atomicOr(&g_fB,1);
    }
}
__global__ void conv_k(const void* __restrict__ m){
    int i=blockIdx.x*blockDim.x+threadIdx.x;
    if(i>=Bv*SK)return;
    int A=g_fA,B=g_fB; bool v;
    if(A&&B)v=((const unsigned char*)m)[i]!=0;
    else if(B)v=((const int*)m)[i]!=0;
    else if(A)v=((const float*)m)[i]!=0.f;
    else v=false;
    g_maskf[i]=v?1.f:0.f;
}

// ---------------- main attention: merged PV(kt)+QK(kt+1) pipeline ----------------
__global__ void __launch_bounds__(512,1)
attn_mma(float* __restrict__ Out){
    extern __shared__ char sm[];
    const uint32_t sb=s2u(sm);
    const int tid=threadIdx.x, wid=tid>>5, lane=tid&31;
    const int bi=blockIdx.x&7, qt=QT-1-(blockIdx.x>>3), q0=qt*BQ;
    const int lr=lane>>2, lc=lane&3, g=lane>>3, rin=lane&7;
    const int g2=g>>1, gk=g&1;
    const int mwQ=wid>>2, nwQ=wid&3;     // QK: 4m x 4n, warp tile 16x16
    const int mw2=wid>>3, nw8=wid&7;     // PV: 2m x 8n, warp tile 32x32

    float* MSKs=(float*)(sm+O_MSK);  float* RMAX=(float*)(sm+O_RMAX);
    float* ALPHA=(float*)(sm+O_ALPHA); float* MROW=(float*)(sm+O_MROW);
    float* LSUM=(float*)(sm+O_LSUM);  float* LINV=(float*)(sm+O_LINV);

    float o[2][4][4];
    #pragma unroll
    for(int a=0;a<2;a++)
        #pragma unroll
        for(int b=0;b<4;b++){o[a][b][0]=0.f;o[a][b][1]=0.f;o[a][b][2]=0.f;o[a][b][3]=0.f;}
    float ls0=0.f, ls1=0.f;
    float c4[2][4];

    const int rA=mwQ*16+gk*8+rin;
    const uint32_t aQH=sb+O_QH+rA*512, aQL=sb+O_QL+rA*512;
    const int rB=nwQ*16+g2*8+rin;
    const uint32_t bKH=sb+O_KH+rB*512, bKL=sb+O_KL+rB*512;
    const int rP=mw2*32+gk*8+rin;
    const uint32_t aPH=sb+O_PH+rP*128, aPL=sb+O_PL+rP*128;
    const int rV=gk*8+rin;
    const uint32_t bVH=sb+O_VH+rV*512, bVL=sb+O_VL+rV*512;
    const int srow0=mwQ*16+lr, srow1=srow0+8;

    const size_t rowQ=(size_t)bi*SQ+q0, rowKV=(size_t)bi*SK;

#define QKS(ks_) { uint32_t ah[4],al[4],bh[4],bl[4]; \
    uint32_t ca=(uint32_t)(((2*(ks_)+g2)^rin)<<4); \
    ldsm4(aQH+ca,ah); ldsm4(aQL+ca,al); \
    uint32_t cb=(uint32_t)(((2*(ks_)+gk)^rin)<<4); \
    ldsm4(bKH+cb,bh); ldsm4(bKL+cb,bl); \
    mma16816(c4[0],ah,bh); mma16816(c4[0],ah,bl); mma16816(c4[0],al,bh); \
    mma16816(c4[1],ah,bh+2); mma16816(c4[1],ah,bl+2); mma16816(c4[1],al,bh+2); }

#define PVS(ks2_) { uint32_t vh0[4],vl0[4],vh1[4],vl1[4]; \
    uint32_t rv=(uint32_t)((ks2_)*16*512); \
    uint32_t cv0=(uint32_t)(((nw8*4+g2)^rin)<<4); \
    uint32_t cv1=(uint32_t)(((nw8*4+2+g2)^rin)<<4); \
    ldsm4t(bVH+rv+cv0,vh0); ldsm4t(bVL+rv+cv0,vl0); \
    ldsm4t(bVH+rv+cv1,vh1); ldsm4t(bVL+rv+cv1,vl1); \
    _Pragma("unroll") \
    for(int mt=0;mt<2;++mt){ \
        uint32_t ph4[4],pl4[4]; \
        uint32_t cp2=(uint32_t)(mt*16*128+(((2*(ks2_)+g2)^rin)<<4)); \
        ldsm4(aPH+cp2,ph4); ldsm4(aPL+cp2,pl4); \
        mma16816(o[mt][0],ph4,vh0); mma16816(o[mt][0],ph4,vl0); mma16816(o[mt][0],pl4,vh0); \
        mma16816(o[mt][1],ph4,vh0+2); mma16816(o[mt][1],ph4,vl0+2); mma16816(o[mt][1],pl4,vh0+2); \
        mma16816(o[mt][2],ph4,vh1); mma16816(o[mt][2],ph4,vl1); mma16816(o[mt][2],pl4,vh1); \
        mma16816(o[mt][3],ph4,vh1+2); mma16816(o[mt][3],ph4,vl1+2); mma16816(o[mt][3],pl4,vh1+2); } }

    // ---- prologue: Q + K(0) in one group; QK(0); mask(0) -> slot 0 ----
    ldtile(sb+O_QH, g_Qh+rowQ*32, tid); ldtile(sb+O_QL, g_Ql+rowQ*32, tid);
    ldtile(sb+O_KH, g_Kh+rowKV*32, tid); ldtile(sb+O_KL, g_Kl+rowKV*32, tid);
    CPCOMMIT();
    if(tid<64){ MROW[tid]=-INFINITY; MSKs[tid]=g_maskf[bi*SK+tid]; }
    CPW0(); __syncthreads();
    c4[0][0]=0.f;c4[0][1]=0.f;c4[0][2]=0.f;c4[0][3]=0.f;
    c4[1][0]=0.f;c4[1][1]=0.f;c4[1][2]=0.f;c4[1][3]=0.f;
    #pragma unroll
    for(int ks=0;ks<16;++ks) QKS(ks);

    for(int kt=0;kt<=qt;++kt){
        const int k0=kt*BK;
        const bool more=(kt<qt);
        // ---- tile row max of S(kt) ----
        float t0=fmaxf(fmaxf(c4[0][0],c4[0][1]),fmaxf(c4[1][0],c4[1][1]));
        float t1=fmaxf(fmaxf(c4[0][2],c4[0][3]),fmaxf(c4[1][2],c4[1][3]));
        t0=fmaxf(t0,__shfl_xor_sync(~0u,t0,1)); t0=fmaxf(t0,__shfl_xor_sync(~0u,t0,2));
        t1=fmaxf(t1,__shfl_xor_sync(~0u,t1,1)); t1=fmaxf(t1,__shfl_xor_sync(~0u,t1,2));
        if(lc==0){ RMAX[nwQ*64+srow0]=t0; RMAX[nwQ*64+srow1]=t1; }
        __syncthreads();  // B1: RMAX visible; merged(kt-1) done -> K,V,P buffers free

        // commits: V1(kt), K-A(kt+1), V2(kt), K-B(kt+1)   (empty groups when !more)
        ldVrow(sb+O_VH, sb+O_VL, g_Vh+(rowKV+k0)*32, g_Vl+(rowKV+k0)*32, 0, tid); CPCOMMIT();
        if(more) ldKdep(sb+O_KH, sb+O_KL, g_Kh+(rowKV+k0+BK)*32, g_Kl+(rowKV+k0+BK)*32, 0, tid);
        CPCOMMIT();
        ldVrow(sb+O_VH, sb+O_VL, g_Vh+(rowKV+k0)*32, g_Vl+(rowKV+k0)*32, 1, tid); CPCOMMIT();
        if(more) ldKdep(sb+O_KH, sb+O_KL, g_Kh+(rowKV+k0+BK)*32, g_Kl+(rowKV+k0+BK)*32, 1, tid);
        CPCOMMIT();

        if(tid<64){
            float tm=fmaxf(fmaxf(RMAX[tid],RMAX[64+tid]),fmaxf(RMAX[128+tid],RMAX[192+tid]));
            float mo=MROW[tid], mn=fmaxf(mo,tm);
            ALPHA[tid]=__expf(mo-mn); MROW[tid]=mn;
        }
        // mask(kt+1) -> OTHER slot; P(kt) below reads slot kt&1 (written last iter / prologue)
        if(more && tid>=64 && tid<128) MSKs[((kt+1)&1)*64+tid-64]=g_maskf[bi*SK+k0+BK+tid-64];
        __syncthreads();  // B2

        // ---- P = exp(S-m)*mask(*causal) -> smem bf16 hi/lo ----
        const float* MSKc=MSKs+(kt&1)*64;
        const float mn0=MROW[srow0], mn1=MROW[srow1];
        const float a0=ALPHA[srow0], a1=ALPHA[srow1];
        float rs0=0.f, rs1=0.f;
        const bool diag=(kt==qt);
        #pragma unroll
        for(int t=0;t<2;++t){
            int col=nwQ*16+t*8+2*lc;
            float mk0=MSKc[col], mk1=MSKc[col+1];
            float p00=__expf(c4[t][0]-mn0)*mk0, p01=__expf(c4[t][1]-mn0)*mk1;
            float p10=__expf(c4[t][2]-mn1)*mk0, p11=__expf(c4[t][3]-mn1)*mk1;
            if(diag){
                if(col>srow0)p00=0.f; if(col+1>srow0)p01=0.f;
                if(col>srow1)p10=0.f; if(col+1>srow1)p11=0.f;
            }
            rs0+=p00+p01; rs1+=p10+p11;
            __nv_bfloat162 h0=__floats2bfloat162_rn(p00,p01);
            __nv_bfloat162 l0=__floats2bfloat162_rn(p00-__low2float(h0),p01-__high2float(h0));
            __nv_bfloat162 h1=__floats2bfloat162_rn(p10,p11);
            __nv_bfloat162 l1=__floats2bfloat162_rn(p10-__low2float(h1),p11-__high2float(h1));
            int ch=nwQ*2+t;
            uint32_t d0=(uint32_t)(srow0*128+((ch^(srow0&7))<<4)+4*lc);
            uint32_t d1=(uint32_t)(srow1*128+((ch^(srow1&7))<<4)+4*lc);
            *(__nv_bfloat162*)(sm+O_PH+d0)=h0; *(__nv_bfloat162*)(sm+O_PL+d0)=l0;
            *(__nv_bfloat162*)(sm+O_PH+d1)=h1; *(__nv_bfloat162*)(sm+O_PL+d1)=l1;
        }
        rs0+=__shfl_xor_sync(~0u,rs0,1); rs0+=__shfl_xor_sync(~0u,rs0,2);
        rs1+=__shfl_xor_sync(~0u,rs1,1); rs1+=__shfl_xor_sync(~0u,rs1,2);
        ls0=ls0*a0+rs0; ls1=ls1*a1+rs1;
        #pragma unroll
        for(int mt=0;mt<2;++mt){
            float am0=ALPHA[mw2*32+mt*16+lr], am1=ALPHA[mw2*32+mt*16+8+lr];
            #pragma unroll
            for(int j=0;j<4;++j){
                o[mt][j][0]*=am0; o[mt][j][1]*=am0; o[mt][j][2]*=am1; o[mt][j][3]*=am1;
            }
        }
        __syncthreads();  // B3: P visible

        // ---- merged: PV(kt) + QK(kt+1), staged cp waits ----
        if(more){
            c4[0][0]=0.f;c4[0][1]=0.f;c4[0][2]=0.f;c4[0][3]=0.f;
            c4[1][0]=0.f;c4[1][1]=0.f;c4[1][2]=0.f;c4[1][3]=0.f;
            CPW3(); PVS(0); PVS(1);
            CPW2(); QKS(0); QKS(1); QKS(2); QKS(3);
            CPW1(); PVS(2); QKS(4); QKS(5); QKS(6); QKS(7);
            CPW0(); PVS(3);
            QKS(8); QKS(9); QKS(10); QKS(11); QKS(12); QKS(13); QKS(14); QKS(15);
        } else {
            CPW3(); PVS(0); PVS(1);
            CPW1(); PVS(2); PVS(3);
        }
    }

    // ---- epilogue ----
    __syncthreads();
    if(lc==0){ LSUM[nwQ*64+srow0]=ls0; LSUM[nwQ*64+srow1]=ls1; }
    __syncthreads();
    if(tid<64) LINV[tid]=1.f/(LSUM[tid]+LSUM[64+tid]+LSUM[128+tid]+LSUM[192+tid]+EPSV);
    __syncthreads();
    #pragma unroll
    for(int mt=0;mt<2;++mt){
        int r0=mw2*32+mt*16+lr, r1=r0+8;
        float i0=LINV[r0], i1=LINV[r1];
        float* out0=Out+(size_t)(bi*SQ+q0+r0)*Dv;
        float* out1=Out+(size_t)(bi*SQ+q0+r1)*Dv;
        #pragma unroll
        for(int j=0;j<4;++j){
            int col=nw8*32+j*8+2*lc;
            *(float2*)(out0+col)=make_float2(o[mt][j][0]*i0,o[mt][j][1]*i0);
            *(float2*)(out1+col)=make_float2(o[mt][j][2]*i1,o[mt][j][3]*i1);
        }
    }
#undef QKS
#undef PVS
}

extern "C" void kernel_launch(void* const* d_in, const int* in_sizes, int n_in,
                              void* d_out, int out_size){
    (void)in_sizes; (void)n_in; (void)out_size;
    const float* Q=(const float*)d_in[0];
    const float* K=(const float*)d_in[1];
    const float* V=(const float*)d_in[2];
    const void*  M=d_in[3];
    float*       O=(float*)d_out;

    zero_k<<<1,1>>>();
    splitqkv_k<<<3*2048,256>>>(Q,K,V,(const unsigned char*)M);
    conv_k<<<(Bv*SK+255)/256,256>>>(M);

    cudaFuncSetAttribute(attn_mma, cudaFuncAttributeMaxDynamicSharedMemorySize, SMEM_SZ);
    attn_mma<<<QT*Bv,512,SMEM_SZ>>>(O);
}

// round 13
// speedup vs baseline: 1.1810x; 1.0341x over previous
#include <cuda_runtime.h>
#include <cuda_bf16.h>
#include <cstdint>
#include <math.h>

namespace {
constexpr int Bv=8, SQ=2048, SK=2048, Dv=256;
constexpr int BQ=64, BK=64, QT=SQ/BQ;   // 32 q-tiles
constexpr float SCALE=0.0625f, EPSV=1e-7f;
// smem byte offsets
constexpr int O_QH=0, O_QL=32768, O_KH=65536, O_KL=98304, O_VH=131072, O_VL=163840;
constexpr int O_PH=196608, O_PL=204800;
constexpr int O_MSK=212992;                       // 128 floats (double-buffered, parity by kt)
constexpr int O_RMAX=213504, O_LSUM=214528, O_LINV=215552;
constexpr int SMEM_SZ=215808;
constexpr size_t NE=(size_t)Bv*SQ*Dv;
}

__device__ uint4 g_Qh[NE/8], g_Ql[NE/8], g_Kh[NE/8], g_Kl[NE/8], g_Vh[NE/8], g_Vl[NE/8];
__device__ float g_maskf[Bv*SK];
__device__ int g_fA, g_fB;

__device__ __forceinline__ uint32_t s2u(const void* p){
    uint32_t a; asm("{ .reg .u64 t; cvta.to.shared.u64 t,%1; cvt.u32.u64 %0,t; }":"=r"(a):"l"(p)); return a;
}
__device__ __forceinline__ void ldsm4(uint32_t a, uint32_t* r){
    asm volatile("ldmatrix.sync.aligned.m8n8.x4.shared.b16 {%0,%1,%2,%3},[%4];"
        :"=r"(r[0]),"=r"(r[1]),"=r"(r[2]),"=r"(r[3]):"r"(a));
}
__device__ __forceinline__ void ldsm4t(uint32_t a, uint32_t* r){
    asm volatile("ldmatrix.sync.aligned.m8n8.x4.trans.shared.b16 {%0,%1,%2,%3},[%4];"
        :"=r"(r[0]),"=r"(r[1]),"=r"(r[2]),"=r"(r[3]):"r"(a));
}
__device__ __forceinline__ void mma16816(float* c, const uint32_t* a, const uint32_t* b){
    asm volatile("mma.sync.aligned.m16n8k16.row.col.f32.bf16.bf16.f32 "
        "{%0,%1,%2,%3},{%4,%5,%6,%7},{%8,%9},{%0,%1,%2,%3};"
        :"+f"(c[0]),"+f"(c[1]),"+f"(c[2]),"+f"(c[3])
        :"r"(a[0]),"r"(a[1]),"r"(a[2]),"r"(a[3]),"r"(b[0]),"r"(b[1]));
}
#define CPCOMMIT() asm volatile("cp.async.commit_group;":::"memory")
#define CPW0() asm volatile("cp.async.wait_group 0;":::"memory")
#define CPW1() asm volatile("cp.async.wait_group 1;":::"memory")
#define CPW2() asm volatile("cp.async.wait_group 2;":::"memory")
#define CPW3() asm volatile("cp.async.wait_group 3;":::"memory")
#define CPA(d,s) asm volatile("cp.async.cg.shared.global [%0],[%1],16;"::"r"(d),"l"(s))

// 64x256 bf16 tile (32KB) gmem -> swizzled smem; 512 threads
__device__ __forceinline__ void ldtile(uint32_t sbase, const uint4* g, int tid){
    #pragma unroll
    for(int i=0;i<4;i++){
        int idx=i*512+tid, r=idx>>5, c=idx&31;
        uint32_t d=sbase+(uint32_t)(((r<<5)+(c^(r&7)))<<4);
        CPA(d, g+(size_t)r*32+c);
    }
}
// depth half h (uint4 cols h*16..h*16+15) of hi+lo 64x256 tiles
__device__ __forceinline__ void ldKdep(uint32_t sH, uint32_t sL, const uint4* gH, const uint4* gL, int h, int tid){
    #pragma unroll
    for(int i=0;i<2;i++){
        int idx=i*512+tid, r=idx>>4, c=(idx&15)+h*16;
        uint32_t d=(uint32_t)(((r<<5)+(c^(r&7)))<<4);
        CPA(sH+d, gH+(size_t)r*32+c);
        CPA(sL+d, gL+(size_t)r*32+c);
    }
}
// row half h (rows h*32..h*32+31) of hi+lo V tiles
__device__ __forceinline__ void ldVrow(uint32_t sH, uint32_t sL, const uint4* gH, const uint4* gL, int h, int tid){
    #pragma unroll
    for(int i=0;i<2;i++){
        int idx=i*512+tid, r=h*32+(idx>>5), c=idx&31;
        uint32_t d=(uint32_t)(((r<<5)+(c^(r&7)))<<4);
        CPA(sH+d, gH+(size_t)r*32+c);
        CPA(sL+d, gL+(size_t)r*32+c);
    }
}

// ---------------- prologues (3 launches) ----------------
__global__ void zero_k(){ g_fA=0; g_fB=0; }
__global__ void splitqkv_k(const float* __restrict__ Q, const float* __restrict__ K,
                           const float* __restrict__ V, const unsigned char* __restrict__ m){
    const int blk=blockIdx.x, which=blk>>11, lb=blk&2047;
    const float* X = which==0?Q:(which==1?K:V);
    uint4* H = which==0?g_Qh:(which==1?g_Kh:g_Vh);
    uint4* L = which==0?g_Ql:(which==1?g_Kl:g_Vl);
    const float sc = which==0?SCALE:1.f;
    size_t i=((size_t)lb*256+threadIdx.x)*8;
    float4 x0=*(const float4*)(X+i), x1=*(const float4*)(X+i+4);
    float v[8]={x0.x,x0.y,x0.z,x0.w,x1.x,x1.y,x1.z,x1.w};
    __nv_bfloat162 h[4], l[4];
    #pragma unroll
    for(int j=0;j<4;j++){
        float a=v[2*j]*sc, b=v[2*j+1]*sc;
        __nv_bfloat162 hh=__floats2bfloat162_rn(a,b);
        h[j]=hh;
        l[j]=__floats2bfloat162_rn(a-__low2float(hh), b-__high2float(hh));
    }
    H[i/8]=*(uint4*)h; L[i/8]=*(uint4*)l;
    if(blk<32){
        int a=0,b=0;
        int base=blk*512+threadIdx.x*2;
        #pragma unroll
        for(int j=0;j<2;j++){
            int idx=base+j;
            if(idx<Bv*SK && m[idx]){ if((idx&3)==0)b=1; else a=1; }
        }
        if(a)atomicOr(&g_fA,1);
        if(b)atomicOr(&g_fB,1);
    }
}
__global__ void conv_k(const void* __restrict__ m){
    int i=blockIdx.x*blockDim.x+threadIdx.x;
    if(i>=Bv*SK)return;
    int A=g_fA,B=g_fB; bool v;
    if(A&&B)v=((const unsigned char*)m)[i]!=0;
    else if(B)v=((const int*)m)[i]!=0;
    else if(A)v=((const float*)m)[i]!=0.f;
    else v=false;
    g_maskf[i]=v?1.f:0.f;
}

// ---------------- main attention: merged pipeline, 2 barriers/tile ----------------
__global__ void __launch_bounds__(512,1)
attn_mma(float* __restrict__ Out){
    extern __shared__ char sm[];
    const uint32_t sb=s2u(sm);
    const int tid=threadIdx.x, wid=tid>>5, lane=tid&31;
    const int bi=blockIdx.x&7, qt=QT-1-(blockIdx.x>>3), q0=qt*BQ;
    const int lr=lane>>2, lc=lane&3, g=lane>>3, rin=lane&7;
    const int g2=g>>1, gk=g&1;
    const int mwQ=wid>>2, nwQ=wid&3;     // QK: 4m x 4n, warp tile 16x16
    const int mw2=wid>>3, nw8=wid&7;     // PV: 2m x 8n, warp tile 32x32

    float* MSKs=(float*)(sm+O_MSK);  float* RMAX=(float*)(sm+O_RMAX);
    float* LSUM=(float*)(sm+O_LSUM); float* LINV=(float*)(sm+O_LINV);

    float o[2][4][4];
    #pragma unroll
    for(int a=0;a<2;a++)
        #pragma unroll
        for(int b=0;b<4;b++){o[a][b][0]=0.f;o[a][b][1]=0.f;o[a][b][2]=0.f;o[a][b][3]=0.f;}
    float ls0=0.f, ls1=0.f;
    float c4[2][4];
    // per-thread running-max state (redundant across lanes; proven in R7)
    float m_s0=-INFINITY, m_s1=-INFINITY;
    float m_o[2][2]={{-INFINITY,-INFINITY},{-INFINITY,-INFINITY}};

    const int rA=mwQ*16+gk*8+rin;
    const uint32_t aQH=sb+O_QH+rA*512, aQL=sb+O_QL+rA*512;
    const int rB=nwQ*16+g2*8+rin;
    const uint32_t bKH=sb+O_KH+rB*512, bKL=sb+O_KL+rB*512;
    const int rP=mw2*32+gk*8+rin;
    const uint32_t aPH=sb+O_PH+rP*128, aPL=sb+O_PL+rP*128;
    const int rV=gk*8+rin;
    const uint32_t bVH=sb+O_VH+rV*512, bVL=sb+O_VL+rV*512;
    const int srow0=mwQ*16+lr, srow1=srow0+8;
    const int orow0=mw2*32+lr;

    const size_t rowQ=(size_t)bi*SQ+q0, rowKV=(size_t)bi*SK;

#define QKS(ks_) { uint32_t ah[4],al[4],bh[4],bl[4]; \
    uint32_t ca=(uint32_t)(((2*(ks_)+g2)^rin)<<4); \
    ldsm4(aQH+ca,ah); ldsm4(aQL+ca,al); \
    uint32_t cb=(uint32_t)(((2*(ks_)+gk)^rin)<<4); \
    ldsm4(bKH+cb,bh); ldsm4(bKL+cb,bl); \
    mma16816(c4[0],ah,bh); mma16816(c4[0],ah,bl); mma16816(c4[0],al,bh); \
    mma16816(c4[1],ah,bh+2); mma16816(c4[1],ah,bl+2); mma16816(c4[1],al,bh+2); }

#define PVS(ks2_) { uint32_t vh0[4],vl0[4],vh1[4],vl1[4]; \
    uint32_t rv=(uint32_t)((ks2_)*16*512); \
    uint32_t cv0=(uint32_t)(((nw8*4+g2)^rin)<<4); \
    uint32_t cv1=(uint32_t)(((nw8*4+2+g2)^rin)<<4); \
    ldsm4t(bVH+rv+cv0,vh0); ldsm4t(bVL+rv+cv0,vl0); \
    ldsm4t(bVH+rv+cv1,vh1); ldsm4t(bVL+rv+cv1,vl1); \
    _Pragma("unroll") \
    for(int mt=0;mt<2;++mt){ \
        uint32_t ph4[4],pl4[4]; \
        uint32_t cp2=(uint32_t)(mt*16*128+(((2*(ks2_)+g2)^rin)<<4)); \
        ldsm4(aPH+cp2,ph4); ldsm4(aPL+cp2,pl4); \
        mma16816(o[mt][0],ph4,vh0); mma16816(o[mt][0],ph4,vl0); mma16816(o[mt][0],pl4,vh0); \
        mma16816(o[mt][1],ph4,vh0+2); mma16816(o[mt][1],ph4,vl0+2); mma16816(o[mt][1],pl4,vh0+2); \
        mma16816(o[mt][2],ph4,vh1); mma16816(o[mt][2],ph4,vl1); mma16816(o[mt][2],pl4,vh1); \
        mma16816(o[mt][3],ph4,vh1+2); mma16816(o[mt][3],ph4,vl1+2); mma16816(o[mt][3],pl4,vh1+2); } }

    // ---- prologue: Q + K(0) in one group; QK(0); mask(0) -> slot 0 ----
    ldtile(sb+O_QH, g_Qh+rowQ*32, tid); ldtile(sb+O_QL, g_Ql+rowQ*32, tid);
    ldtile(sb+O_KH, g_Kh+rowKV*32, tid); ldtile(sb+O_KL, g_Kl+rowKV*32, tid);
    CPCOMMIT();
    if(tid<64) MSKs[tid]=g_maskf[bi*SK+tid];
    CPW0(); __syncthreads();
    c4[0][0]=0.f;c4[0][1]=0.f;c4[0][2]=0.f;c4[0][3]=0.f;
    c4[1][0]=0.f;c4[1][1]=0.f;c4[1][2]=0.f;c4[1][3]=0.f;
    #pragma unroll
    for(int ks=0;ks<16;++ks) QKS(ks);

    for(int kt=0;kt<=qt;++kt){
        const int k0=kt*BK;
        const bool more=(kt<qt);
        // ---- tile row max of S(kt) ----
        float t0=fmaxf(fmaxf(c4[0][0],c4[0][1]),fmaxf(c4[1][0],c4[1][1]));
        float t1=fmaxf(fmaxf(c4[0][2],c4[0][3]),fmaxf(c4[1][2],c4[1][3]));
        t0=fmaxf(t0,__shfl_xor_sync(~0u,t0,1)); t0=fmaxf(t0,__shfl_xor_sync(~0u,t0,2));
        t1=fmaxf(t1,__shfl_xor_sync(~0u,t1,1)); t1=fmaxf(t1,__shfl_xor_sync(~0u,t1,2));
        if(lc==0){ RMAX[nwQ*64+srow0]=t0; RMAX[nwQ*64+srow1]=t1; }
        __syncthreads();  // B1: RMAX visible; merged(kt-1) done -> K,V,P buffers free

        // commits: V1(kt), K-A(kt+1), V2(kt), K-B(kt+1)   (empty groups when !more)
        ldVrow(sb+O_VH, sb+O_VL, g_Vh+(rowKV+k0)*32, g_Vl+(rowKV+k0)*32, 0, tid); CPCOMMIT();
        if(more) ldKdep(sb+O_KH, sb+O_KL, g_Kh+(rowKV+k0+BK)*32, g_Kl+(rowKV+k0+BK)*32, 0, tid);
        CPCOMMIT();
        ldVrow(sb+O_VH, sb+O_VL, g_Vh+(rowKV+k0)*32, g_Vl+(rowKV+k0)*32, 1, tid); CPCOMMIT();
        if(more) ldKdep(sb+O_KH, sb+O_KL, g_Kh+(rowKV+k0+BK)*32, g_Kl+(rowKV+k0+BK)*32, 1, tid);
        CPCOMMIT();
        // mask(kt+1) -> OTHER slot (reads below use slot kt&1)
        if(more && tid>=64 && tid<128) MSKs[((kt+1)&1)*64+tid-64]=g_maskf[bi*SK+k0+BK+tid-64];

        // ---- per-thread running max / alpha (reads RMAX(kt); pre-B3) ----
        float v0=fmaxf(fmaxf(RMAX[srow0],RMAX[64+srow0]),fmaxf(RMAX[128+srow0],RMAX[192+srow0]));
        float v1=fmaxf(fmaxf(RMAX[srow1],RMAX[64+srow1]),fmaxf(RMAX[128+srow1],RMAX[192+srow1]));
        const float mn0=fmaxf(m_s0,v0), mn1=fmaxf(m_s1,v1);
        const float a0=__expf(m_s0-mn0), a1=__expf(m_s1-mn1);
        m_s0=mn0; m_s1=mn1;
        float ao[2][2];
        #pragma unroll
        for(int mt=0;mt<2;++mt)
            #pragma unroll
            for(int h=0;h<2;++h){
                int rr=orow0+mt*16+h*8;
                float tv=fmaxf(fmaxf(RMAX[rr],RMAX[64+rr]),fmaxf(RMAX[128+rr],RMAX[192+rr]));
                float mo=fmaxf(m_o[mt][h],tv);
                ao[mt][h]=__expf(m_o[mt][h]-mo);
                m_o[mt][h]=mo;
            }

        // ---- P = exp(S-m)*mask(*causal) -> smem bf16 hi/lo ----
        const float* MSKc=MSKs+(kt&1)*64;
        float rs0=0.f, rs1=0.f;
        const bool diag=(kt==qt);
        #pragma unroll
        for(int t=0;t<2;++t){
            int col=nwQ*16+t*8+2*lc;
            float mk0=MSKc[col], mk1=MSKc[col+1];
            float p00=__expf(c4[t][0]-mn0)*mk0, p01=__expf(c4[t][1]-mn0)*mk1;
            float p10=__expf(c4[t][2]-mn1)*mk0, p11=__expf(c4[t][3]-mn1)*mk1;
            if(diag){
                if(col>srow0)p00=0.f; if(col+1>srow0)p01=0.f;
                if(col>srow1)p10=0.f; if(col+1>srow1)p11=0.f;
            }
            rs0+=p00+p01; rs1+=p10+p11;
            __nv_bfloat162 h0=__floats2bfloat162_rn(p00,p01);
            __nv_bfloat162 l0=__floats2bfloat162_rn(p00-__low2float(h0),p01-__high2float(h0));
            __nv_bfloat162 h1=__floats2bfloat162_rn(p10,p11);
            __nv_bfloat162 l1=__floats2bfloat162_rn(p10-__low2float(h1),p11-__high2float(h1));
            int ch=nwQ*2+t;
            uint32_t d0=(uint32_t)(srow0*128+((ch^(srow0&7))<<4)+4*lc);
            uint32_t d1=(uint32_t)(srow1*128+((ch^(srow1&7))<<4)+4*lc);
            *(__nv_bfloat162*)(sm+O_PH+d0)=h0; *(__nv_bfloat162*)(sm+O_PL+d0)=l0;
            *(__nv_bfloat162*)(sm+O_PH+d1)=h1; *(__nv_bfloat162*)(sm+O_PL+d1)=l1;
        }
        rs0+=__shfl_xor_sync(~0u,rs0,1); rs0+=__shfl_xor_sync(~0u,rs0,2);
        rs1+=__shfl_xor_sync(~0u,rs1,1); rs1+=__shfl_xor_sync(~0u,rs1,2);
        ls0=ls0*a0+rs0; ls1=ls1*a1+rs1;
        #pragma unroll
        for(int mt=0;mt<2;++mt){
            #pragma unroll
            for(int j=0;j<4;++j){
                o[mt][j][0]*=ao[mt][0]; o[mt][j][1]*=ao[mt][0];
                o[mt][j][2]*=ao[mt][1]; o[mt][j][3]*=ao[mt][1];
            }
        }
        __syncthreads();  // B3: P visible (also orders RMAX(kt) reads before (kt+1) writes)

        // ---- merged: PV(kt) + QK(kt+1), staged cp waits ----
        if(more){
            c4[0][0]=0.f;c4[0][1]=0.f;c4[0][2]=0.f;c4[0][3]=0.f;
            c4[1][0]=0.f;c4[1][1]=0.f;c4[1][2]=0.f;c4[1][3]=0.f;
            CPW3(); PVS(0); PVS(1);
            CPW2(); QKS(0); QKS(1); QKS(2); QKS(3);
            CPW1(); PVS(2); QKS(4); QKS(5); QKS(6); QKS(7);
            CPW0(); PVS(3);
            QKS(8); QKS(9); QKS(10); QKS(11); QKS(12); QKS(13); QKS(14); QKS(15);
        } else {
            CPW3(); PVS(0); PVS(1);
            CPW1(); PVS(2); PVS(3);
        }
    }

    // ---- epilogue ----
    __syncthreads();
    if(lc==0){ LSUM[nwQ*64+srow0]=ls0; LSUM[nwQ*64+srow1]=ls1; }
    __syncthreads();
    if(tid<64) LINV[tid]=1.f/(LSUM[tid]+LSUM[64+tid]+LSUM[128+tid]+LSUM[192+tid]+EPSV);
    __syncthreads();
    #pragma unroll
    for(int mt=0;mt<2;++mt){
        int r0=mw2*32+mt*16+lr, r1=r0+8;
        float i0=LINV[r0], i1=LINV[r1];
        float* out0=Out+(size_t)(bi*SQ+q0+r0)*Dv;
        float* out1=Out+(size_t)(bi*SQ+q0+r1)*Dv;
        #pragma unroll
        for(int j=0;j<4;++j){
            int col=nw8*32+j*8+2*lc;
            *(float2*)(out0+col)=make_float2(o[mt][j][0]*i0,o[mt][j][1]*i0);
            *(float2*)(out1+col)=make_float2(o[mt][j][2]*i1,o[mt][j][3]*i1);
        }
    }
#undef QKS
#undef PVS
}

extern "C" void kernel_launch(void* const* d_in, const int* in_sizes, int n_in,
                              void* d_out, int out_size){
    (void)in_sizes; (void)n_in; (void)out_size;
    const float* Q=(const float*)d_in[0];
    const float* K=(const float*)d_in[1];
    const float* V=(const float*)d_in[2];
    const void*  M=d_in[3];
    float*       O=(float*)d_out;

    zero_k<<<1,1>>>();
    splitqkv_k<<<3*2048,256>>>(Q,K,V,(const unsigned char*)M);
    conv_k<<<(Bv*SK+255)/256,256>>>(M);

    cudaFuncSetAttribute(attn_mma, cudaFuncAttributeMaxDynamicSharedMemorySize, SMEM_SZ);
    attn_mma<<<QT*Bv,512,SMEM_SZ>>>(O);
}